// round 6
// baseline (speedup 1.0000x reference)
#include <cuda_runtime.h>
#include <cuda_bf16.h>
#include <cstdint>
#include <math.h>

#define BSZ 4
#define TLEN 2048
#define CDIM 1024
#define BT (BSZ*TLEN)            // 8192
#define TOT ((long long)BT*CDIM)
#define N2 (CDIM*CDIM)

typedef __nv_bfloat16 bf16;

// ---------------- scratch (device globals; no cudaMalloc allowed) ----------
__device__ float g_q0[BT*CDIM];
__device__ float g_q1[BT*CDIM];
__device__ float g_vc[BT*CDIM];
__device__ float g_v [BT*CDIM];
__device__ float g_X0[N2];
__device__ float g_X1[N2];
__device__ float g_Am[N2];
__device__ bf16 g_ga_hi[BT*CDIM], g_ga_lo[BT*CDIM];     // big A operand splits
__device__ bf16 g_gb_hi[N2], g_gb_lo[N2];               // W_up/W_v/W_proj splits
__device__ bf16 g_xh[2][N2], g_xl[2][N2];               // X splits (ping-pong)
__device__ bf16 g_xth[2][N2], g_xtl[2][N2];             // X^T splits (ping-pong)
__device__ bf16 g_ah[N2], g_al[N2];                     // A = X^T X splits
__device__ bf16 g_sh[N2], g_sl[N2];                     // S splits

// ---------------- PTX helpers ----------------------------------------------
__device__ __forceinline__ uint32_t smem_u32(const void* p) {
    uint32_t a;
    asm("{ .reg .u64 t; cvta.to.shared.u64 t, %1; cvt.u32.u64 %0, t; }" : "=r"(a) : "l"(p));
    return a;
}
__device__ __forceinline__ void cp16(uint32_t dst, const void* src) {
    asm volatile("cp.async.cg.shared.global [%0], [%1], 16;" :: "r"(dst), "l"(src));
}
__device__ __forceinline__ void ldsm4(uint32_t a, uint32_t* r) {
    asm volatile("ldmatrix.sync.aligned.m8n8.x4.shared.b16 {%0,%1,%2,%3}, [%4];"
                 : "=r"(r[0]), "=r"(r[1]), "=r"(r[2]), "=r"(r[3]) : "r"(a));
}
__device__ __forceinline__ void mma16816(float* c, const uint32_t* a, const uint32_t* b) {
    asm volatile("mma.sync.aligned.m16n8k16.row.col.f32.bf16.bf16.f32 "
        "{%0,%1,%2,%3}, {%4,%5,%6,%7}, {%8,%9}, {%0,%1,%2,%3};"
        : "+f"(c[0]), "+f"(c[1]), "+f"(c[2]), "+f"(c[3])
        : "r"(a[0]), "r"(a[1]), "r"(a[2]), "r"(a[3]), "r"(b[0]), "r"(b[1]));
}

// ---------------- HMMA bf16-split GEMM --------------------------------------
// C[M,N] = alpha * (A @ B^T) + beta * Cin. A: MxK row-major, B: NxK row-major,
// K = 1024. A = Ahi+Alo, B = Bhi+Blo (3-product fp32 emulation).
// CTA tile: 128 x (32*WN). Warp grid 4 x WN, warp tile 32x32. 128*WN threads.
// 3-stage cp.async pipeline, ONE __syncthreads per K-tile.
template<int WN>
__device__ __forceinline__ void load_stage_t(uint32_t stg,
    const bf16* __restrict__ Ahi, const bf16* __restrict__ Alo,
    const bf16* __restrict__ Bhi, const bf16* __restrict__ Blo,
    int m0, int n0, int k0, int tid)
{
    constexpr int BN = 32*WN;
    constexpr int THREADS = 128*WN;
    constexpr int TILE_A_BY = 128*144;
    constexpr int TILE_B_BY = BN*144;
    constexpr int ITERS = (256 + 2*BN)*8/THREADS;
    #pragma unroll
    for (int t = 0; t < ITERS; t++) {
        int i = tid + t*THREADS;
        int r_all = i >> 3;
        int c = (i & 7) << 3;
        uint32_t dst; const bf16* src;
        if (r_all < 128) {
            dst = stg + r_all*144 + c*2;
            src = Ahi + (long long)(m0+r_all)*CDIM + k0 + c;
        } else if (r_all < 256) {
            int r = r_all - 128;
            dst = stg + TILE_A_BY + r*144 + c*2;
            src = Alo + (long long)(m0+r)*CDIM + k0 + c;
        } else if (r_all < 256+BN) {
            int r = r_all - 256;
            dst = stg + 2*TILE_A_BY + r*144 + c*2;
            src = Bhi + (long long)(n0+r)*CDIM + k0 + c;
        } else {
            int r = r_all - 256 - BN;
            dst = stg + 2*TILE_A_BY + TILE_B_BY + r*144 + c*2;
            src = Blo + (long long)(n0+r)*CDIM + k0 + c;
        }
        cp16(dst, src);
    }
}

template<int WN>
__global__ void __launch_bounds__(128*WN, 1) mma_gemm(
    const bf16* __restrict__ Ahi, const bf16* __restrict__ Alo,
    const bf16* __restrict__ Bhi, const bf16* __restrict__ Blo,
    float* __restrict__ Cout, const float* __restrict__ Cin,
    bf16* __restrict__ Chi, bf16* __restrict__ Clo,
    bf16* __restrict__ CThi, bf16* __restrict__ CTlo,
    int M, int N, float alpha, float beta)
{
    constexpr int BN = 32*WN;
    constexpr int THREADS = 128*WN;
    constexpr int TILE_A_BY = 128*144;
    constexpr int TILE_B_BY = BN*144;
    constexpr int STG_BY = 2*TILE_A_BY + 2*TILE_B_BY;

    extern __shared__ char smem[];
    const uint32_t sb = smem_u32(smem);
    const int tid = threadIdx.x, wid = tid >> 5, lane = tid & 31;
    const int m0 = blockIdx.y * 128, n0 = blockIdx.x * BN;
    const int warp_m = wid & 3;     // 4 warps along M (32 rows each)
    const int warp_n = wid >> 2;    // WN warps along N (32 cols each)

    float acc[2][4][4];
    #pragma unroll
    for (int a = 0; a < 2; a++)
        #pragma unroll
        for (int b = 0; b < 4; b++)
            #pragma unroll
            for (int c = 0; c < 4; c++) acc[a][b][c] = 0.0f;

    // A (x4): lanes 0-15 -> rows, lanes>=16 -> k+8 halves
    const uint32_t a_base = (warp_m*32 + (lane & 15))*144 + ((lane >> 4) << 4);
    // B (x4, non-trans): lanes 0-7 n0-7/k0-7, 8-15 n0-7/k8-15, 16-23 n8-15/k0-7, 24-31 n8-15/k8-15
    const uint32_t b_base = (warp_n*32 + (lane & 7) + ((lane >> 4) << 3))*144
                          + (((lane >> 3) & 1) << 4);

    // prologue: stages 0,1
    load_stage_t<WN>(sb, Ahi, Alo, Bhi, Blo, m0, n0, 0, tid);
    asm volatile("cp.async.commit_group;" ::: "memory");
    load_stage_t<WN>(sb + STG_BY, Ahi, Alo, Bhi, Blo, m0, n0, 64, tid);
    asm volatile("cp.async.commit_group;" ::: "memory");

    for (int kt = 0; kt < 16; kt++) {
        if (kt < 15) asm volatile("cp.async.wait_group 1;" ::: "memory");
        else         asm volatile("cp.async.wait_group 0;" ::: "memory");
        __syncthreads();   // stage kt ready; all warps done reading stage (kt+2)%3
        if (kt + 2 < 16) {
            load_stage_t<WN>(sb + ((kt+2)%3)*STG_BY, Ahi, Alo, Bhi, Blo, m0, n0, (kt+2)*64, tid);
            asm volatile("cp.async.commit_group;" ::: "memory");
        }

        const uint32_t stg = sb + (kt%3)*STG_BY;
        #pragma unroll
        for (int kc = 0; kc < 4; kc++) {
            uint32_t ah[2][4], al[2][4], bh[2][4], bl[2][4];
            const uint32_t ao = stg + a_base + kc*32;
            ldsm4(ao,                       ah[0]);
            ldsm4(ao + 16*144,              ah[1]);
            ldsm4(ao + TILE_A_BY,           al[0]);
            ldsm4(ao + TILE_A_BY + 16*144,  al[1]);
            const uint32_t bo = stg + 2*TILE_A_BY + b_base + kc*32;
            ldsm4(bo,                       bh[0]);
            ldsm4(bo + 16*144,              bh[1]);
            ldsm4(bo + TILE_B_BY,           bl[0]);
            ldsm4(bo + TILE_B_BY + 16*144,  bl[1]);
            #pragma unroll
            for (int mt = 0; mt < 2; mt++)
                #pragma unroll
                for (int nt = 0; nt < 4; nt++) {
                    const int n2 = nt >> 1, hf = (nt & 1) << 1;
                    mma16816(acc[mt][nt], ah[mt], &bh[n2][hf]);
                    mma16816(acc[mt][nt], ah[mt], &bl[n2][hf]);
                    mma16816(acc[mt][nt], al[mt], &bh[n2][hf]);
                }
        }
    }
    __syncthreads();   // all compute done; smem free for epilogue staging

    // ---- epilogue ----
    constexpr int STRD = BN + 5;       // float stride for transpose staging
    float* st = (float*)smem;
    const bool doCT = (CThi != nullptr);
    const int qr = lane >> 2, qc = (lane & 3) << 1;

    #pragma unroll
    for (int mt = 0; mt < 2; mt++) {
        #pragma unroll
        for (int nt = 0; nt < 4; nt++) {
            const int lr = warp_m*32 + mt*16 + qr;
            const int lc = warp_n*32 + nt*8 + qc;
            const int row = m0 + lr, col = n0 + lc;
            float* c = acc[mt][nt];
            const long long i0 = (long long)row*N + col;
            const long long i1 = (long long)(row+8)*N + col;
            float v0 = alpha*c[0], v1 = alpha*c[1], v2 = alpha*c[2], v3 = alpha*c[3];
            if (Cin) {
                float2 c0 = *(const float2*)(Cin + i0);
                float2 c1 = *(const float2*)(Cin + i1);
                v0 += beta*c0.x; v1 += beta*c0.y; v2 += beta*c1.x; v3 += beta*c1.y;
            }
            if (Cout) {
                *(float2*)(Cout + i0) = make_float2(v0, v1);
                *(float2*)(Cout + i1) = make_float2(v2, v3);
            }
            if (Chi) {
                bf16 h0 = __float2bfloat16(v0), h1 = __float2bfloat16(v1);
                bf16 h2 = __float2bfloat16(v2), h3 = __float2bfloat16(v3);
                *(__nv_bfloat162*)(Chi + i0) = __nv_bfloat162(h0, h1);
                *(__nv_bfloat162*)(Chi + i1) = __nv_bfloat162(h2, h3);
                *(__nv_bfloat162*)(Clo + i0) = __nv_bfloat162(
                    __float2bfloat16(v0 - __bfloat162float(h0)),
                    __float2bfloat16(v1 - __bfloat162float(h1)));
                *(__nv_bfloat162*)(Clo + i1) = __nv_bfloat162(
                    __float2bfloat16(v2 - __bfloat162float(h2)),
                    __float2bfloat16(v3 - __bfloat162float(h3)));
            }
            if (doCT) {
                st[lr*STRD + lc]     = v0;
                st[lr*STRD + lc+1]   = v1;
                st[(lr+8)*STRD + lc]   = v2;
                st[(lr+8)*STRD + lc+1] = v3;
            }
        }
    }
    if (doCT) {
        __syncthreads();
        // write transposed splits: CT[(n0+n)*M + m0+m] = tile[m][n]
        for (int idx = tid; idx < BN*64; idx += THREADS) {
            const int n = idx >> 6;
            const int m = (idx & 63) << 1;
            float v0 = st[m*STRD + n];
            float v1 = st[(m+1)*STRD + n];
            bf16 h0 = __float2bfloat16(v0), h1 = __float2bfloat16(v1);
            const long long o = (long long)(n0+n)*M + (m0+m);
            *(__nv_bfloat162*)(CThi + o) = __nv_bfloat162(h0, h1);
            *(__nv_bfloat162*)(CTlo + o) = __nv_bfloat162(
                __float2bfloat16(v0 - __bfloat162float(h0)),
                __float2bfloat16(v1 - __bfloat162float(h1)));
        }
    }
}

static constexpr int SMEM_BIG = 3*(2*128*144 + 2*128*144);   // 221184
static constexpr int SMEM_NS  = 3*(2*128*144 + 2*64*144);    // 165888

// ---------------- elementwise kernels ----------------------------------------
__global__ void convert_split(const float* __restrict__ src,
                              bf16* __restrict__ hi, bf16* __restrict__ lo, long long n) {
    long long i = (long long)blockIdx.x*blockDim.x + threadIdx.x;
    if (i >= n) return;
    float x = src[i];
    bf16 h = __float2bfloat16(x);
    hi[i] = h; lo[i] = __float2bfloat16(x - __bfloat162float(h));
}
// X0 = scale*Wraw; write fp32, splits, transposed splits
__global__ void init_X(const float* __restrict__ src, float scale, float* __restrict__ X,
                       bf16* __restrict__ xh, bf16* __restrict__ xl,
                       bf16* __restrict__ xth, bf16* __restrict__ xtl) {
    __shared__ float t[32][33];
    const int bx = blockIdx.x*32, by = blockIdx.y*32;
    const int tx = threadIdx.x, ty = threadIdx.y;  // 32x8
    #pragma unroll
    for (int j = 0; j < 32; j += 8) {
        long long o = (long long)(by+ty+j)*CDIM + bx + tx;
        float v = src[o]*scale;
        X[o] = v;
        bf16 h = __float2bfloat16(v);
        xh[o] = h; xl[o] = __float2bfloat16(v - __bfloat162float(h));
        t[ty+j][tx] = v;
    }
    __syncthreads();
    #pragma unroll
    for (int j = 0; j < 32; j += 8) {
        float v = t[tx][ty+j];
        bf16 h = __float2bfloat16(v);
        long long o = (long long)(bx+ty+j)*CDIM + by + tx;
        xth[o] = h; xtl[o] = __float2bfloat16(v - __bfloat162float(h));
    }
}
__global__ void shift_add_split(const float* __restrict__ cur, const float* __restrict__ ident,
                                bf16* __restrict__ uhi, bf16* __restrict__ ulo, int d) {
    long long i = (long long)blockIdx.x*blockDim.x + threadIdx.x;
    if (i >= TOT) return;
    long long t = i >> 10;
    int c = (int)(i & 1023);
    int tt = (int)(t % TLEN);
    float leftv = (tt >= d) ? cur[i - (long long)d*CDIM] : ident[c];
    float s = leftv + cur[i];
    bf16 h = __float2bfloat16(s);
    uhi[i] = h; ulo[i] = __float2bfloat16(s - __bfloat162float(h));
}
__global__ void mul_split(const float* __restrict__ a, const float* __restrict__ b,
                          bf16* __restrict__ hi, bf16* __restrict__ lo) {
    long long i = (long long)blockIdx.x*blockDim.x + threadIdx.x;
    if (i >= TOT) return;
    float x = a[i]*b[i];
    bf16 h = __float2bfloat16(x);
    hi[i] = h; lo[i] = __float2bfloat16(x - __bfloat162float(h));
}

// ---------------- combine: tiny 4-lane SDPA + rmsnorm per token -------------
__global__ void combine_kernel(const float* __restrict__ cur, const float* __restrict__ vc,
                               const float* __restrict__ ident, float* __restrict__ nxt, int d) {
    const int t = blockIdx.x, tt = t % TLEN, j = threadIdx.x;
    const float* left  = (tt >= d) ? (cur + (long long)(t-d)*CDIM) : ident;
    const float* right = cur + (long long)t*CDIM;
    const float* vv    = vc  + (long long)t*CDIM;
    float l[4], r[4], w[4];
    #pragma unroll
    for (int i = 0; i < 4; i++) { l[i]=left[i*256+j]; r[i]=right[i*256+j]; w[i]=vv[i*256+j]; }
    __shared__ float red[16][8];
    __shared__ float scores[16];
    __shared__ float scale_s[4];
    const int lane = j & 31, warp = j >> 5;
    #pragma unroll
    for (int q = 0; q < 16; q++) {
        float v = l[q>>2]*r[q&3];
        #pragma unroll
        for (int o = 16; o > 0; o >>= 1) v += __shfl_down_sync(0xffffffffu, v, o);
        if (lane == 0) red[q][warp] = v;
    }
    __syncthreads();
    if (j < 16) {
        float s = 0.f;
        #pragma unroll
        for (int wq = 0; wq < 8; wq++) s += red[j][wq];
        scores[j] = s * 0.0625f;
    }
    __syncthreads();
    float att[4][4];
    #pragma unroll
    for (int a = 0; a < 4; a++) {
        float mx = scores[a*4];
        #pragma unroll
        for (int b = 1; b < 4; b++) mx = fmaxf(mx, scores[a*4+b]);
        float sm = 0.f;
        #pragma unroll
        for (int b = 0; b < 4; b++) { att[a][b] = expf(scores[a*4+b]-mx); sm += att[a][b]; }
        float inv = 1.0f/sm;
        #pragma unroll
        for (int b = 0; b < 4; b++) att[a][b] *= inv;
    }
    float z[4];
    #pragma unroll
    for (int a = 0; a < 4; a++)
        z[a] = att[a][0]*w[0] + att[a][1]*w[1] + att[a][2]*w[2] + att[a][3]*w[3];
    __syncthreads();
    #pragma unroll
    for (int a = 0; a < 4; a++) {
        float v = z[a]*z[a];
        #pragma unroll
        for (int o = 16; o > 0; o >>= 1) v += __shfl_down_sync(0xffffffffu, v, o);
        if (lane == 0) red[a][warp] = v;
    }
    __syncthreads();
    if (j < 4) {
        float s = 0.f;
        #pragma unroll
        for (int wq = 0; wq < 8; wq++) s += red[j][wq];
        scale_s[j] = rsqrtf(s*(1.0f/256.0f) + 1e-8f) / (float)(j+1);
    }
    __syncthreads();
    float* o = nxt + (long long)t*CDIM;
    #pragma unroll
    for (int a = 0; a < 4; a++) o[a*256+j] = l[a] + z[a]*scale_s[a];
}

// ---------------- host orchestration ----------------------------------------
static inline void gemmBig(const bf16* Ahi, const bf16* Alo, const bf16* Bhi, const bf16* Blo,
                           float* Cout, const float* Cin, int M, int N, float alpha, float beta)
{
    dim3 grid(N/128, M/128);
    mma_gemm<4><<<grid, 512, SMEM_BIG>>>(Ahi, Alo, Bhi, Blo, Cout, Cin,
                                         nullptr, nullptr, nullptr, nullptr, M, N, alpha, beta);
}
static inline void gemmNS(const bf16* Ahi, const bf16* Alo, const bf16* Bhi, const bf16* Blo,
                          float* Cout, const float* Cin,
                          bf16* Chi, bf16* Clo, bf16* CThi, bf16* CTlo,
                          float alpha, float beta)
{
    dim3 grid(CDIM/64, CDIM/128);
    mma_gemm<2><<<grid, 256, SMEM_NS>>>(Ahi, Alo, Bhi, Blo, Cout, Cin,
                                        Chi, Clo, CThi, CTlo, CDIM, CDIM, alpha, beta);
}

extern "C" void kernel_launch(void* const* d_in, const int* in_sizes, int n_in,
                              void* d_out, int out_size)
{
    const float* x      = (const float*)d_in[0];
    const float* W_up   = (const float*)d_in[1];
    const float* W_v    = (const float*)d_in[2];
    const float* W_proj = (const float*)d_in[3];
    const float* ident  = (const float*)d_in[4];
    const float* W_raw  = (const float*)d_in[5];
    float* out = (float*)d_out;
    const long long half = (long long)out_size / 2;

    cudaFuncSetAttribute(mma_gemm<4>, cudaFuncAttributeMaxDynamicSharedMemorySize, SMEM_BIG);
    cudaFuncSetAttribute(mma_gemm<2>, cudaFuncAttributeMaxDynamicSharedMemorySize, SMEM_NS);

    float *q0,*q1,*vc,*v,*X0,*X1,*Am;
    bf16 *gah,*gal,*gbh,*gbl,*ah,*al,*sh,*sl;
    bf16 *xh[2],*xl[2],*xth[2],*xtl[2];
    cudaGetSymbolAddress((void**)&q0, g_q0);
    cudaGetSymbolAddress((void**)&q1, g_q1);
    cudaGetSymbolAddress((void**)&vc, g_vc);
    cudaGetSymbolAddress((void**)&v , g_v );
    cudaGetSymbolAddress((void**)&X0, g_X0);
    cudaGetSymbolAddress((void**)&X1, g_X1);
    cudaGetSymbolAddress((void**)&Am, g_Am);
    cudaGetSymbolAddress((void**)&gah, g_ga_hi); cudaGetSymbolAddress((void**)&gal, g_ga_lo);
    cudaGetSymbolAddress((void**)&gbh, g_gb_hi); cudaGetSymbolAddress((void**)&gbl, g_gb_lo);
    cudaGetSymbolAddress((void**)&ah, g_ah); cudaGetSymbolAddress((void**)&al, g_al);
    cudaGetSymbolAddress((void**)&sh, g_sh); cudaGetSymbolAddress((void**)&sl, g_sl);
    { bf16* p; cudaGetSymbolAddress((void**)&p, g_xh);  xh[0]=p;  xh[1]=p+N2; }
    { bf16* p; cudaGetSymbolAddress((void**)&p, g_xl);  xl[0]=p;  xl[1]=p+N2; }
    { bf16* p; cudaGetSymbolAddress((void**)&p, g_xth); xth[0]=p; xth[1]=p+N2; }
    { bf16* p; cudaGetSymbolAddress((void**)&p, g_xtl); xtl[0]=p; xtl[1]=p+N2; }

    const long long WN_ = (long long)N2;
    const int wb = (int)((WN_ + 255)/256);
    const int eb = (int)((TOT + 255)/256);
    dim3 tgrid(32, 32), tblk(32, 8);

    // ---- 1) polar factor via quintic (Muon) + cubic polish ----
    init_X<<<tgrid, tblk>>>(W_raw, 1.0f/1.35f, X0, xh[0], xl[0], xth[0], xtl[0]);
    float* Xc = X0; float* Xn = X1;
    int pp = 0;
    const float qa = 3.4445f, qb = -4.7750f, qc5 = 2.0315f;
    for (int it = 0; it < 9; it++) {
        gemmNS(xth[pp], xtl[pp], xth[pp], xtl[pp], Am, nullptr,
               ah, al, nullptr, nullptr, 1.0f, 0.0f);                 // A = X^T X
        gemmNS(ah, al, ah, al, nullptr, Am,
               sh, sl, nullptr, nullptr, qc5, qb);                    // S = c*A^2 + b*A
        gemmNS(xh[pp], xl[pp], sh, sl, Xn, Xc,
               xh[pp^1], xl[pp^1], xth[pp^1], xtl[pp^1], 1.0f, qa);   // Xn = X S + a X
        float* tmp = Xc; Xc = Xn; Xn = tmp; pp ^= 1;
    }
    for (int it = 0; it < 4; it++) {
        gemmNS(xth[pp], xtl[pp], xth[pp], xtl[pp], nullptr, nullptr,
               ah, al, nullptr, nullptr, 1.0f, 0.0f);                 // A = X^T X
        gemmNS(xh[pp], xl[pp], ah, al, Xn, Xc,
               xh[pp^1], xl[pp^1], xth[pp^1], xtl[pp^1], -0.5f, 1.5f);// Xn = 1.5X - 0.5 X A
        float* tmp = Xc; Xc = Xn; Xn = tmp; pp ^= 1;
    }
    bf16* wth = xth[pp];   // W^T splits for scan (vc = u @ W, NT form)
    bf16* wtl = xtl[pp];

    // ---- 2) q0 = x @ W_up^T ; v = x @ W_v^T ----
    convert_split<<<eb,256>>>(x, gah, gal, TOT);
    convert_split<<<wb,256>>>(W_up, gbh, gbl, WN_);
    gemmBig(gah, gal, gbh, gbl, q0, nullptr, BT, CDIM, 1.0f, 0.0f);
    convert_split<<<wb,256>>>(W_v, gbh, gbl, WN_);
    gemmBig(gah, gal, gbh, gbl, v, nullptr, BT, CDIM, 1.0f, 0.0f);

    // ---- 3) parallel scan: 11 Hillis-Steele steps ----
    float* cur = q0; float* nxt = q1;
    for (int d = 1; d < TLEN; d <<= 1) {
        shift_add_split<<<eb,256>>>(cur, ident, gah, gal, d);
        gemmBig(gah, gal, wth, wtl, vc, nullptr, BT, CDIM, 1.0f, 0.0f);
        combine_kernel<<<BT,256>>>(cur, vc, ident, nxt, d);
        float* tmp = cur; cur = nxt; nxt = tmp;
    }

    // ---- 4) Y = (q*v) @ W_proj^T ; write (Y, q) ----
    mul_split<<<eb,256>>>(cur, v, gah, gal);
    convert_split<<<wb,256>>>(W_proj, gbh, gbl, WN_);
    gemmBig(gah, gal, gbh, gbl, out, nullptr, BT, CDIM, 1.0f, 0.0f);
    cudaMemcpyAsync(out + half, cur, half*sizeof(float), cudaMemcpyDeviceToDevice, 0);
}

// round 7
// speedup vs baseline: 1.0410x; 1.0410x over previous
#include <cuda_runtime.h>
#include <cuda_bf16.h>
#include <cstdint>
#include <math.h>

#define BSZ 4
#define TLEN 2048
#define CDIM 1024
#define BT (BSZ*TLEN)            // 8192
#define TOT ((long long)BT*CDIM)
#define N2 (CDIM*CDIM)

typedef __nv_bfloat16 bf16;

// ---------------- scratch (device globals; no cudaMalloc allowed) ----------
__device__ float g_q0[BT*CDIM];
__device__ float g_q1[BT*CDIM];
__device__ float g_vc[BT*CDIM];
__device__ float g_v [BT*CDIM];
__device__ float g_X0[N2];
__device__ float g_X1[N2];
__device__ float g_Am[N2];
__device__ bf16 g_ga_hi[BT*CDIM], g_ga_lo[BT*CDIM];     // big A operand splits
__device__ bf16 g_gb_hi[N2], g_gb_lo[N2];               // W_up/W_v/W_proj splits
__device__ bf16 g_xh[2][N2], g_xl[2][N2];               // X splits (ping-pong)
__device__ bf16 g_xth[2][N2], g_xtl[2][N2];             // X^T splits (ping-pong)
__device__ bf16 g_ah[N2], g_al[N2];                     // A = X^T X splits
__device__ bf16 g_sh[N2], g_sl[N2];                     // S splits

// ---------------- PTX helpers ----------------------------------------------
__device__ __forceinline__ uint32_t smem_u32(const void* p) {
    uint32_t a;
    asm("{ .reg .u64 t; cvta.to.shared.u64 t, %1; cvt.u32.u64 %0, t; }" : "=r"(a) : "l"(p));
    return a;
}
__device__ __forceinline__ void cp16(uint32_t dst, const void* src) {
    asm volatile("cp.async.cg.shared.global [%0], [%1], 16;" :: "r"(dst), "l"(src));
}
__device__ __forceinline__ void ldsm4(uint32_t a, uint32_t* r) {
    asm volatile("ldmatrix.sync.aligned.m8n8.x4.shared.b16 {%0,%1,%2,%3}, [%4];"
                 : "=r"(r[0]), "=r"(r[1]), "=r"(r[2]), "=r"(r[3]) : "r"(a));
}
__device__ __forceinline__ void mma16816(float* c, const uint32_t* a, const uint32_t* b) {
    asm volatile("mma.sync.aligned.m16n8k16.row.col.f32.bf16.bf16.f32 "
        "{%0,%1,%2,%3}, {%4,%5,%6,%7}, {%8,%9}, {%0,%1,%2,%3};"
        : "+f"(c[0]), "+f"(c[1]), "+f"(c[2]), "+f"(c[3])
        : "r"(a[0]), "r"(a[1]), "r"(a[2]), "r"(a[3]), "r"(b[0]), "r"(b[1]));
}
__device__ __forceinline__ uint32_t pk(float a, float b) {
    __nv_bfloat162 t(__float2bfloat16(a), __float2bfloat16(b));
    return *(uint32_t*)&t;
}

// ---------------- HMMA bf16-split GEMM --------------------------------------
// C[M,N] = alpha * (A @ B^T) + beta * Cin. A: MxK row-major, B: NxK row-major,
// K = 1024. A = Ahi+Alo, B = Bhi+Blo (3-product fp32 emulation).
// CTA tile 128x64, BK=32, 3-stage cp.async, 256 threads (4M x 2N warps, 32x32
// warp tile), 2 CTAs/SM. Optional epilogue: fp32, bf16 splits, transposed splits.
static constexpr int RSTR = 80;                 // smem row stride bytes (32 bf16 + pad)
static constexpr int TILE_A_BY = 128*RSTR;      // 10240
static constexpr int TILE_B_BY = 64*RSTR;       // 5120
static constexpr int STG_BY = 2*TILE_A_BY + 2*TILE_B_BY;  // 30720
static constexpr int GEMM_SMEM = 3*STG_BY;      // 92160

__device__ __forceinline__ void load_stage(uint32_t stg,
    const bf16* __restrict__ Ahi, const bf16* __restrict__ Alo,
    const bf16* __restrict__ Bhi, const bf16* __restrict__ Blo,
    int m0, int n0, int k0, int tid)
{
    // 384 rows x 4 chunks of 16B = 1536 cp16 / 256 threads = 6 iters
    #pragma unroll
    for (int t = 0; t < 6; t++) {
        int i = tid + t*256;
        int r_all = i >> 2;
        int c = (i & 3) << 3;                 // elem col 0,8,16,24
        uint32_t dst; const bf16* src;
        if (r_all < 128) {
            dst = stg + r_all*RSTR + c*2;
            src = Ahi + (long long)(m0+r_all)*CDIM + k0 + c;
        } else if (r_all < 256) {
            int r = r_all - 128;
            dst = stg + TILE_A_BY + r*RSTR + c*2;
            src = Alo + (long long)(m0+r)*CDIM + k0 + c;
        } else if (r_all < 320) {
            int r = r_all - 256;
            dst = stg + 2*TILE_A_BY + r*RSTR + c*2;
            src = Bhi + (long long)(n0+r)*CDIM + k0 + c;
        } else {
            int r = r_all - 320;
            dst = stg + 2*TILE_A_BY + TILE_B_BY + r*RSTR + c*2;
            src = Blo + (long long)(n0+r)*CDIM + k0 + c;
        }
        cp16(dst, src);
    }
}

__global__ void __launch_bounds__(256, 2) mma_gemm(
    const bf16* __restrict__ Ahi, const bf16* __restrict__ Alo,
    const bf16* __restrict__ Bhi, const bf16* __restrict__ Blo,
    float* __restrict__ Cout, const float* __restrict__ Cin,
    bf16* __restrict__ Chi, bf16* __restrict__ Clo,
    bf16* __restrict__ CThi, bf16* __restrict__ CTlo,
    int M, int N, float alpha, float beta)
{
    extern __shared__ char smem[];
    const uint32_t sb = smem_u32(smem);
    const int tid = threadIdx.x, wid = tid >> 5, lane = tid & 31;
    const int m0 = blockIdx.y * 128, n0 = blockIdx.x * 64;
    const int warp_m = wid & 3;     // 4 warps along M (32 rows each)
    const int warp_n = wid >> 2;    // 2 warps along N (32 cols each)

    float acc[2][4][4];
    #pragma unroll
    for (int a = 0; a < 2; a++)
        #pragma unroll
        for (int b = 0; b < 4; b++)
            #pragma unroll
            for (int c = 0; c < 4; c++) acc[a][b][c] = 0.0f;

    const uint32_t a_base = (warp_m*32 + (lane & 15))*RSTR + ((lane >> 4) << 4);
    const uint32_t b_base = (warp_n*32 + (lane & 7) + ((lane >> 4) << 3))*RSTR
                          + (((lane >> 3) & 1) << 4);

    // prologue: stages 0,1
    load_stage(sb, Ahi, Alo, Bhi, Blo, m0, n0, 0, tid);
    asm volatile("cp.async.commit_group;" ::: "memory");
    load_stage(sb + STG_BY, Ahi, Alo, Bhi, Blo, m0, n0, 32, tid);
    asm volatile("cp.async.commit_group;" ::: "memory");

    for (int kt = 0; kt < 32; kt++) {
        if (kt < 31) asm volatile("cp.async.wait_group 1;" ::: "memory");
        else         asm volatile("cp.async.wait_group 0;" ::: "memory");
        __syncthreads();   // stage kt ready; all warps done reading stage (kt+2)%3
        if (kt + 2 < 32) {
            load_stage(sb + ((kt+2)%3)*STG_BY, Ahi, Alo, Bhi, Blo, m0, n0, (kt+2)*32, tid);
            asm volatile("cp.async.commit_group;" ::: "memory");
        }

        const uint32_t stg = sb + (kt%3)*STG_BY;
        #pragma unroll
        for (int kc = 0; kc < 2; kc++) {
            uint32_t ah[2][4], al[2][4], bh[2][4], bl[2][4];
            const uint32_t ao = stg + a_base + kc*32;
            ldsm4(ao,                        ah[0]);
            ldsm4(ao + 16*RSTR,              ah[1]);
            ldsm4(ao + TILE_A_BY,            al[0]);
            ldsm4(ao + TILE_A_BY + 16*RSTR,  al[1]);
            const uint32_t bo = stg + 2*TILE_A_BY + b_base + kc*32;
            ldsm4(bo,                        bh[0]);
            ldsm4(bo + 16*RSTR,              bh[1]);
            ldsm4(bo + TILE_B_BY,            bl[0]);
            ldsm4(bo + TILE_B_BY + 16*RSTR,  bl[1]);
            #pragma unroll
            for (int mt = 0; mt < 2; mt++)
                #pragma unroll
                for (int nt = 0; nt < 4; nt++) {
                    const int n2 = nt >> 1, hf = (nt & 1) << 1;
                    mma16816(acc[mt][nt], ah[mt], &bh[n2][hf]);
                    mma16816(acc[mt][nt], ah[mt], &bl[n2][hf]);
                    mma16816(acc[mt][nt], al[mt], &bh[n2][hf]);
                }
        }
    }
    __syncthreads();   // compute done; smem free for epilogue staging

    // ---- epilogue ----
    constexpr int STRD = 64 + 5;       // float stride for transpose staging
    float* st = (float*)smem;
    const bool doCT = (CThi != nullptr);
    const int qr = lane >> 2, qc = (lane & 3) << 1;

    #pragma unroll
    for (int mt = 0; mt < 2; mt++) {
        #pragma unroll
        for (int nt = 0; nt < 4; nt++) {
            const int lr = warp_m*32 + mt*16 + qr;
            const int lc = warp_n*32 + nt*8 + qc;
            const int row = m0 + lr, col = n0 + lc;
            float* c = acc[mt][nt];
            const long long i0 = (long long)row*N + col;
            const long long i1 = (long long)(row+8)*N + col;
            float v0 = alpha*c[0], v1 = alpha*c[1], v2 = alpha*c[2], v3 = alpha*c[3];
            if (Cin) {
                float2 c0 = *(const float2*)(Cin + i0);
                float2 c1 = *(const float2*)(Cin + i1);
                v0 += beta*c0.x; v1 += beta*c0.y; v2 += beta*c1.x; v3 += beta*c1.y;
            }
            if (Cout) {
                *(float2*)(Cout + i0) = make_float2(v0, v1);
                *(float2*)(Cout + i1) = make_float2(v2, v3);
            }
            if (Chi) {
                uint32_t h0 = pk(v0, v1), h1 = pk(v2, v3);
                *(uint32_t*)(Chi + i0) = h0;
                *(uint32_t*)(Chi + i1) = h1;
                __nv_bfloat162 hh0 = *(__nv_bfloat162*)&h0;
                __nv_bfloat162 hh1 = *(__nv_bfloat162*)&h1;
                *(uint32_t*)(Clo + i0) = pk(v0 - __bfloat162float(hh0.x),
                                            v1 - __bfloat162float(hh0.y));
                *(uint32_t*)(Clo + i1) = pk(v2 - __bfloat162float(hh1.x),
                                            v3 - __bfloat162float(hh1.y));
            }
            if (doCT) {
                st[lr*STRD + lc]       = v0;
                st[lr*STRD + lc+1]     = v1;
                st[(lr+8)*STRD + lc]   = v2;
                st[(lr+8)*STRD + lc+1] = v3;
            }
        }
    }
    if (doCT) {
        __syncthreads();
        // write transposed splits: CT[(n0+n)*M + m0+m] = tile[m][n]
        for (int idx = tid; idx < 64*64; idx += 256) {
            const int n = idx >> 6;
            const int m = (idx & 63) << 1;
            float v0 = st[m*STRD + n];
            float v1 = st[(m+1)*STRD + n];
            uint32_t h = pk(v0, v1);
            const long long o = (long long)(n0+n)*M + (m0+m);
            *(uint32_t*)(CThi + o) = h;
            __nv_bfloat162 hh = *(__nv_bfloat162*)&h;
            *(uint32_t*)(CTlo + o) = pk(v0 - __bfloat162float(hh.x),
                                        v1 - __bfloat162float(hh.y));
        }
    }
}

// ---------------- elementwise kernels (vectorized x4) ------------------------
__global__ void convert_split4(const float* __restrict__ src,
                               bf16* __restrict__ hi, bf16* __restrict__ lo, long long n4) {
    long long i = (long long)blockIdx.x*blockDim.x + threadIdx.x;
    if (i >= n4) return;
    long long i4 = i*4;
    float4 x = *(const float4*)(src + i4);
    uint32_t h0 = pk(x.x, x.y), h1 = pk(x.z, x.w);
    *(uint2*)(hi + i4) = make_uint2(h0, h1);
    __nv_bfloat162 a = *(__nv_bfloat162*)&h0, b = *(__nv_bfloat162*)&h1;
    *(uint2*)(lo + i4) = make_uint2(
        pk(x.x - __bfloat162float(a.x), x.y - __bfloat162float(a.y)),
        pk(x.z - __bfloat162float(b.x), x.w - __bfloat162float(b.y)));
}
// X0 = scale*Wraw; write fp32, splits, transposed splits
__global__ void init_X(const float* __restrict__ src, float scale, float* __restrict__ X,
                       bf16* __restrict__ xh, bf16* __restrict__ xl,
                       bf16* __restrict__ xth, bf16* __restrict__ xtl) {
    __shared__ float t[32][33];
    const int bx = blockIdx.x*32, by = blockIdx.y*32;
    const int tx = threadIdx.x, ty = threadIdx.y;  // 32x8
    #pragma unroll
    for (int j = 0; j < 32; j += 8) {
        long long o = (long long)(by+ty+j)*CDIM + bx + tx;
        float v = src[o]*scale;
        X[o] = v;
        bf16 h = __float2bfloat16(v);
        xh[o] = h; xl[o] = __float2bfloat16(v - __bfloat162float(h));
        t[ty+j][tx] = v;
    }
    __syncthreads();
    #pragma unroll
    for (int j = 0; j < 32; j += 8) {
        float v = t[tx][ty+j];
        bf16 h = __float2bfloat16(v);
        long long o = (long long)(bx+ty+j)*CDIM + by + tx;
        xth[o] = h; xtl[o] = __float2bfloat16(v - __bfloat162float(h));
    }
}
__global__ void shift_add_split4(const float* __restrict__ cur, const float* __restrict__ ident,
                                 bf16* __restrict__ uhi, bf16* __restrict__ ulo, int d) {
    long long i = (long long)blockIdx.x*blockDim.x + threadIdx.x;
    if (i >= TOT/4) return;
    long long i4 = i*4;
    long long t = i4 >> 10;
    int c = (int)(i4 & 1023);
    int tt = (int)(t % TLEN);
    float4 rv = *(const float4*)(cur + i4);
    float4 lv = (tt >= d) ? *(const float4*)(cur + i4 - (long long)d*CDIM)
                          : *(const float4*)(ident + c);
    float s0 = lv.x + rv.x, s1 = lv.y + rv.y, s2 = lv.z + rv.z, s3 = lv.w + rv.w;
    uint32_t h0 = pk(s0, s1), h1 = pk(s2, s3);
    *(uint2*)(uhi + i4) = make_uint2(h0, h1);
    __nv_bfloat162 a = *(__nv_bfloat162*)&h0, b = *(__nv_bfloat162*)&h1;
    *(uint2*)(ulo + i4) = make_uint2(
        pk(s0 - __bfloat162float(a.x), s1 - __bfloat162float(a.y)),
        pk(s2 - __bfloat162float(b.x), s3 - __bfloat162float(b.y)));
}
__global__ void mul_split4(const float* __restrict__ a, const float* __restrict__ b,
                           bf16* __restrict__ hi, bf16* __restrict__ lo) {
    long long i = (long long)blockIdx.x*blockDim.x + threadIdx.x;
    if (i >= TOT/4) return;
    long long i4 = i*4;
    float4 x = *(const float4*)(a + i4);
    float4 y = *(const float4*)(b + i4);
    float s0 = x.x*y.x, s1 = x.y*y.y, s2 = x.z*y.z, s3 = x.w*y.w;
    uint32_t h0 = pk(s0, s1), h1 = pk(s2, s3);
    *(uint2*)(hi + i4) = make_uint2(h0, h1);
    __nv_bfloat162 p = *(__nv_bfloat162*)&h0, q = *(__nv_bfloat162*)&h1;
    *(uint2*)(lo + i4) = make_uint2(
        pk(s0 - __bfloat162float(p.x), s1 - __bfloat162float(p.y)),
        pk(s2 - __bfloat162float(q.x), s3 - __bfloat162float(q.y)));
}

// ---------------- combine: tiny 4-lane SDPA + rmsnorm per token -------------
__global__ void combine_kernel(const float* __restrict__ cur, const float* __restrict__ vc,
                               const float* __restrict__ ident, float* __restrict__ nxt, int d) {
    const int t = blockIdx.x, tt = t % TLEN, j = threadIdx.x;
    const float* left  = (tt >= d) ? (cur + (long long)(t-d)*CDIM) : ident;
    const float* right = cur + (long long)t*CDIM;
    const float* vv    = vc  + (long long)t*CDIM;
    float l[4], r[4], w[4];
    #pragma unroll
    for (int i = 0; i < 4; i++) { l[i]=left[i*256+j]; r[i]=right[i*256+j]; w[i]=vv[i*256+j]; }
    __shared__ float red[16][8];
    __shared__ float scores[16];
    __shared__ float scale_s[4];
    const int lane = j & 31, warp = j >> 5;
    #pragma unroll
    for (int q = 0; q < 16; q++) {
        float v = l[q>>2]*r[q&3];
        #pragma unroll
        for (int o = 16; o > 0; o >>= 1) v += __shfl_down_sync(0xffffffffu, v, o);
        if (lane == 0) red[q][warp] = v;
    }
    __syncthreads();
    if (j < 16) {
        float s = 0.f;
        #pragma unroll
        for (int wq = 0; wq < 8; wq++) s += red[j][wq];
        scores[j] = s * 0.0625f;
    }
    __syncthreads();
    float att[4][4];
    #pragma unroll
    for (int a = 0; a < 4; a++) {
        float mx = scores[a*4];
        #pragma unroll
        for (int b = 1; b < 4; b++) mx = fmaxf(mx, scores[a*4+b]);
        float sm = 0.f;
        #pragma unroll
        for (int b = 0; b < 4; b++) { att[a][b] = expf(scores[a*4+b]-mx); sm += att[a][b]; }
        float inv = 1.0f/sm;
        #pragma unroll
        for (int b = 0; b < 4; b++) att[a][b] *= inv;
    }
    float z[4];
    #pragma unroll
    for (int a = 0; a < 4; a++)
        z[a] = att[a][0]*w[0] + att[a][1]*w[1] + att[a][2]*w[2] + att[a][3]*w[3];
    __syncthreads();
    #pragma unroll
    for (int a = 0; a < 4; a++) {
        float v = z[a]*z[a];
        #pragma unroll
        for (int o = 16; o > 0; o >>= 1) v += __shfl_down_sync(0xffffffffu, v, o);
        if (lane == 0) red[a][warp] = v;
    }
    __syncthreads();
    if (j < 4) {
        float s = 0.f;
        #pragma unroll
        for (int wq = 0; wq < 8; wq++) s += red[j][wq];
        scale_s[j] = rsqrtf(s*(1.0f/256.0f) + 1e-8f) / (float)(j+1);
    }
    __syncthreads();
    float* o = nxt + (long long)t*CDIM;
    #pragma unroll
    for (int a = 0; a < 4; a++) o[a*256+j] = l[a] + z[a]*scale_s[a];
}

// ---------------- host orchestration ----------------------------------------
static inline void gemmBig(const bf16* Ahi, const bf16* Alo, const bf16* Bhi, const bf16* Blo,
                           float* Cout, const float* Cin, int M, int N, float alpha, float beta)
{
    dim3 grid(N/64, M/128);
    mma_gemm<<<grid, 256, GEMM_SMEM>>>(Ahi, Alo, Bhi, Blo, Cout, Cin,
                                       nullptr, nullptr, nullptr, nullptr, M, N, alpha, beta);
}
static inline void gemmNS(const bf16* Ahi, const bf16* Alo, const bf16* Bhi, const bf16* Blo,
                          float* Cout, const float* Cin,
                          bf16* Chi, bf16* Clo, bf16* CThi, bf16* CTlo,
                          float alpha, float beta)
{
    dim3 grid(CDIM/64, CDIM/128);
    mma_gemm<<<grid, 256, GEMM_SMEM>>>(Ahi, Alo, Bhi, Blo, Cout, Cin,
                                       Chi, Clo, CThi, CTlo, CDIM, CDIM, alpha, beta);
}

extern "C" void kernel_launch(void* const* d_in, const int* in_sizes, int n_in,
                              void* d_out, int out_size)
{
    const float* x      = (const float*)d_in[0];
    const float* W_up   = (const float*)d_in[1];
    const float* W_v    = (const float*)d_in[2];
    const float* W_proj = (const float*)d_in[3];
    const float* ident  = (const float*)d_in[4];
    const float* W_raw  = (const float*)d_in[5];
    float* out = (float*)d_out;
    const long long half = (long long)out_size / 2;

    cudaFuncSetAttribute(mma_gemm, cudaFuncAttributeMaxDynamicSharedMemorySize, GEMM_SMEM);

    float *q0,*q1,*vc,*v,*X0,*X1,*Am;
    bf16 *gah,*gal,*gbh,*gbl,*ah,*al,*sh,*sl;
    bf16 *xh[2],*xl[2],*xth[2],*xtl[2];
    cudaGetSymbolAddress((void**)&q0, g_q0);
    cudaGetSymbolAddress((void**)&q1, g_q1);
    cudaGetSymbolAddress((void**)&vc, g_vc);
    cudaGetSymbolAddress((void**)&v , g_v );
    cudaGetSymbolAddress((void**)&X0, g_X0);
    cudaGetSymbolAddress((void**)&X1, g_X1);
    cudaGetSymbolAddress((void**)&Am, g_Am);
    cudaGetSymbolAddress((void**)&gah, g_ga_hi); cudaGetSymbolAddress((void**)&gal, g_ga_lo);
    cudaGetSymbolAddress((void**)&gbh, g_gb_hi); cudaGetSymbolAddress((void**)&gbl, g_gb_lo);
    cudaGetSymbolAddress((void**)&ah, g_ah); cudaGetSymbolAddress((void**)&al, g_al);
    cudaGetSymbolAddress((void**)&sh, g_sh); cudaGetSymbolAddress((void**)&sl, g_sl);
    { bf16* p; cudaGetSymbolAddress((void**)&p, g_xh);  xh[0]=p;  xh[1]=p+N2; }
    { bf16* p; cudaGetSymbolAddress((void**)&p, g_xl);  xl[0]=p;  xl[1]=p+N2; }
    { bf16* p; cudaGetSymbolAddress((void**)&p, g_xth); xth[0]=p; xth[1]=p+N2; }
    { bf16* p; cudaGetSymbolAddress((void**)&p, g_xtl); xtl[0]=p; xtl[1]=p+N2; }

    const int wb4 = (N2/4 + 255)/256;            // 1024
    const int eb4 = (int)((TOT/4 + 255)/256);    // 8192
    dim3 tgrid(32, 32), tblk(32, 8);

    // ---- 1) polar factor via quintic (Muon) + cubic polish ----
    init_X<<<tgrid, tblk>>>(W_raw, 1.0f/1.35f, X0, xh[0], xl[0], xth[0], xtl[0]);
    float* Xc = X0; float* Xn = X1;
    int pp = 0;
    const float qa = 3.4445f, qb = -4.7750f, qc5 = 2.0315f;
    for (int it = 0; it < 9; it++) {
        gemmNS(xth[pp], xtl[pp], xth[pp], xtl[pp], Am, nullptr,
               ah, al, nullptr, nullptr, 1.0f, 0.0f);                 // A = X^T X
        gemmNS(ah, al, ah, al, nullptr, Am,
               sh, sl, nullptr, nullptr, qc5, qb);                    // S = c*A^2 + b*A
        gemmNS(xh[pp], xl[pp], sh, sl, Xn, Xc,
               xh[pp^1], xl[pp^1], xth[pp^1], xtl[pp^1], 1.0f, qa);   // Xn = X S + a X
        float* tmp = Xc; Xc = Xn; Xn = tmp; pp ^= 1;
    }
    for (int it = 0; it < 4; it++) {
        gemmNS(xth[pp], xtl[pp], xth[pp], xtl[pp], nullptr, nullptr,
               ah, al, nullptr, nullptr, 1.0f, 0.0f);                 // A = X^T X
        gemmNS(xh[pp], xl[pp], ah, al, Xn, Xc,
               xh[pp^1], xl[pp^1], xth[pp^1], xtl[pp^1], -0.5f, 1.5f);// Xn = 1.5X - 0.5 X A
        float* tmp = Xc; Xc = Xn; Xn = tmp; pp ^= 1;
    }
    bf16* wth = xth[pp];   // W^T splits for scan (vc = u @ W, NT form)
    bf16* wtl = xtl[pp];

    // ---- 2) q0 = x @ W_up^T ; v = x @ W_v^T ----
    convert_split4<<<eb4,256>>>(x, gah, gal, TOT/4);
    convert_split4<<<wb4,256>>>(W_up, gbh, gbl, N2/4);
    gemmBig(gah, gal, gbh, gbl, q0, nullptr, BT, CDIM, 1.0f, 0.0f);
    convert_split4<<<wb4,256>>>(W_v, gbh, gbl, N2/4);
    gemmBig(gah, gal, gbh, gbl, v, nullptr, BT, CDIM, 1.0f, 0.0f);

    // ---- 3) parallel scan: 11 Hillis-Steele steps ----
    float* cur = q0; float* nxt = q1;
    for (int d = 1; d < TLEN; d <<= 1) {
        shift_add_split4<<<eb4,256>>>(cur, ident, gah, gal, d);
        gemmBig(gah, gal, wth, wtl, vc, nullptr, BT, CDIM, 1.0f, 0.0f);
        combine_kernel<<<BT,256>>>(cur, vc, ident, nxt, d);
        float* tmp = cur; cur = nxt; nxt = tmp;
    }

    // ---- 4) Y = (q*v) @ W_proj^T ; write (Y, q) ----
    mul_split4<<<eb4,256>>>(cur, v, gah, gal);
    convert_split4<<<wb4,256>>>(W_proj, gbh, gbl, N2/4);
    gemmBig(gah, gal, gbh, gbl, out, nullptr, BT, CDIM, 1.0f, 0.0f);
    cudaMemcpyAsync(out + half, cur, half*sizeof(float), cudaMemcpyDeviceToDevice, 0);
}